// round 7
// baseline (speedup 1.0000x reference)
#include <cuda_runtime.h>

// Shapes
#define BB   2
#define CC   4
#define HH   160
#define WW   160
#define DD   96
#define HOUT 154
#define WOUT 154
#define DOUT 90
#define CHST (160*160*96)          // x channel stride (elements)

#define X_ELEMS (BB*CC*HH*WW*DD)   // 19,660,800
#define Y_ELEMS (BB*1*HH*WW*DD)    //  4,915,200

// Intermediate: per (b, h, wo, do): A[4], B[4] (f32), N packed (4 x u8)
#define NPOS (BB*HH*WOUT*DOUT)     // 2*160*154*90 = 4,435,200

__device__ float4   g_A[NPOS];
__device__ float4   g_B[NPOS];
__device__ unsigned g_N[NPOS];
__device__ double   g_acc;
__device__ int      g_ystride;     // 1 = y is int32, 2 = y is int64 (read low words)

// ---------------- dtype probe: int64 y has all-zero odd 32-bit words ----------------
__global__ void k_probe(const int* __restrict__ Y)
{
    __shared__ unsigned acc[256];
    unsigned v = 0;
    // scan first 8192 ints (well within min possible buffer size)
    for (int i = threadIdx.x; i < 4096; i += 256)
        v |= (unsigned)Y[2 * i + 1];
    acc[threadIdx.x] = v;
    __syncthreads();
    for (int s = 128; s > 0; s >>= 1) {
        if (threadIdx.x < s) acc[threadIdx.x] |= acc[threadIdx.x + s];
        __syncthreads();
    }
    if (threadIdx.x == 0) {
        g_ystride = (acc[0] == 0u) ? 2 : 1;
        g_acc = 0.0;
    }
}

// ---------------- K1: voxel -> D-window -> W-window sums ----------------
#define WOC  20             // output wo per chunk
#define WINC 26             // input w per chunk (WOC+6)
#define K1_THREADS 256

// smem layout (bytes):
//   sa  float [WINC*96]  = 9984
//   sb  float [WINC*96]  = 9984
//   sk  u8    [WINC*96]  = 2496      (total 22464, 16B aligned)
//   s2A float4[WINC*90]  = 37440
//   s2B float4[WINC*90]  = 37440
//   s2N u32   [WINC*90]  = 9360
#define SMEM1 (22464 + 37440 + 37440 + 9360)

__global__ __launch_bounds__(K1_THREADS) void k1(const float* __restrict__ X,
                                                 const int* __restrict__ Y)
{
    extern __shared__ char sm[];
    float* sa = (float*)sm;
    float* sb = sa + WINC * 96;
    unsigned char* sk = (unsigned char*)(sb + WINC * 96);
    float4* s2A = (float4*)(sm + 22464);
    float4* s2B = s2A + WINC * 90;
    unsigned* s2N = (unsigned*)(s2B + WINC * 90);

    const int chunk = blockIdx.x;
    const int h     = blockIdx.y;
    const int b     = blockIdx.z;
    const int wb    = chunk * WOC;
    const int woc   = min(WOC, WOUT - wb);   // outputs this chunk
    const int wic   = woc + 6;               // inputs this chunk
    const int tid   = threadIdx.x;
    const int ys    = g_ystride;

    // ---- Stage A: per-voxel a = sigmoid(x[y]) - 0.5, b = a^2, class k ----
    const float* Xb = X + (size_t)b * 4 * CHST + (size_t)h * (WW * DD);
    const int*   Yb = Y + (size_t)ys * ((size_t)b * ((size_t)HH * WW * DD) + (size_t)h * (WW * DD));
    for (int i = tid; i < wic * 96; i += K1_THREADS) {
        int wl = i / 96;
        int d  = i - wl * 96;
        int off = (wb + wl) * 96 + d;
        int k = Yb[off * ys];                // stride 1 (int32) or 2 (int64 low word)
        float x0 = Xb[off];
        float x1 = Xb[off + CHST];
        float x2 = Xb[off + 2 * CHST];
        float x3 = Xb[off + 3 * CHST];
        float v = (k == 0) ? x0 : (k == 1) ? x1 : (k == 2) ? x2 : x3;
        float t = __fdividef(1.0f, 1.0f + __expf(-v));
        float a = t - 0.5f;
        sa[i] = a;
        sb[i] = a * a;
        sk[i] = (unsigned char)k;
    }
    __syncthreads();

    // ---- Stage B: window-7 sum along D, per class ----
    for (int i = tid; i < wic * 90; i += K1_THREADS) {
        int wl = i / 90;
        int dd = i - wl * 90;
        int base = wl * 96 + dd;
        float A0 = 0.f, A1 = 0.f, A2 = 0.f, A3 = 0.f;
        float B0 = 0.f, B1 = 0.f, B2 = 0.f, B3 = 0.f;
        unsigned n = 0u;
        #pragma unroll
        for (int j = 0; j < 7; ++j) {
            int idx = base + j;
            float a  = sa[idx];
            float bq = sb[idx];
            int   k  = sk[idx];
            A0 += (k == 0) ? a : 0.f;  B0 += (k == 0) ? bq : 0.f;
            A1 += (k == 1) ? a : 0.f;  B1 += (k == 1) ? bq : 0.f;
            A2 += (k == 2) ? a : 0.f;  B2 += (k == 2) ? bq : 0.f;
            A3 += (k == 3) ? a : 0.f;  B3 += (k == 3) ? bq : 0.f;
            n  += 1u << (k * 8);
        }
        s2A[i] = make_float4(A0, A1, A2, A3);
        s2B[i] = make_float4(B0, B1, B2, B3);
        s2N[i] = n;
    }
    __syncthreads();

    // ---- Stage C: window-7 sum along W, write intermediate ----
    for (int i = tid; i < woc * 90; i += K1_THREADS) {
        int wl = i / 90;
        int dd = i - wl * 90;
        float4 A = make_float4(0.f, 0.f, 0.f, 0.f);
        float4 B = make_float4(0.f, 0.f, 0.f, 0.f);
        unsigned n = 0u;
        #pragma unroll
        for (int j = 0; j < 7; ++j) {
            int p = (wl + j) * 90 + dd;
            float4 a4 = s2A[p];
            float4 b4 = s2B[p];
            A.x += a4.x; A.y += a4.y; A.z += a4.z; A.w += a4.w;
            B.x += b4.x; B.y += b4.y; B.z += b4.z; B.w += b4.w;
            n += s2N[p];                       // per-byte max 49, no carry
        }
        size_t g = (((size_t)(b * HH + h)) * WOUT + (wb + wl)) * DOUT + dd;
        g_A[g] = A;
        g_B[g] = B;
        g_N[g] = n;
    }
}

// ---------------- K2: sliding window-7 along H + finalize + reduce ----------------
#define SEG 20
#define HS  (WOUT * DOUT)

__device__ __forceinline__ float s_class(float A, float B, float Nf)
{
    const float inv343 = 1.0f / 343.0f;
    const float K2C = 49.0f / 48.0f;
    const float K4C = K2C * K2C;
    const float Cc  = 0.00045f;                // (0.03*1)^2/2
    float yb  = Nf * inv343;
    float g1  = 1.0f - yb;
    float Ab  = A * inv343;
    float Bb  = B * inv343;
    float num = fmaf(K2C * Ab, g1, Cc);
    float var = fmaf(-Ab, Ab, Bb);             // >= 0 (Cauchy-Schwarz)
    float den = fmaf((K4C * var) * yb, g1, Cc);
    return __fdividef(num, den);
}

__global__ __launch_bounds__(360) void k2()
{
    __shared__ float red[360];
    const int tx  = threadIdx.x;               // 0..89 -> do
    const int ty  = threadIdx.y;               // 0..3  -> wo offset
    const int tid = ty * 90 + tx;
    const int wo  = blockIdx.x * 4 + ty;
    const int h0  = blockIdx.y * SEG;
    const int b   = blockIdx.z;
    const int segN = min(SEG, HOUT - h0);
    const bool act = (wo < WOUT);

    float4 sA = make_float4(0.f, 0.f, 0.f, 0.f);
    float4 sB = make_float4(0.f, 0.f, 0.f, 0.f);
    unsigned s02 = 0u, s13 = 0u;               // dual 16-bit lanes: classes {0,2},{1,3}
    float lsum = 0.f;

    size_t base = (size_t)b * HH * HS + (size_t)wo * DOUT + tx;

    if (act) {
        for (int h = h0; h < h0 + segN + 6; ++h) {
            size_t g = base + (size_t)h * HS;
            float4 a4 = g_A[g];
            float4 b4 = g_B[g];
            unsigned n = g_N[g];
            sA.x += a4.x; sA.y += a4.y; sA.z += a4.z; sA.w += a4.w;
            sB.x += b4.x; sB.y += b4.y; sB.z += b4.z; sB.w += b4.w;
            s02 += n & 0x00FF00FFu;
            s13 += (n >> 8) & 0x00FF00FFu;

            if (h - h0 >= 7) {
                size_t go = base + (size_t)(h - 7) * HS;
                float4 a4o = g_A[go];
                float4 b4o = g_B[go];
                unsigned no = g_N[go];
                sA.x -= a4o.x; sA.y -= a4o.y; sA.z -= a4o.z; sA.w -= a4o.w;
                sB.x -= b4o.x; sB.y -= b4o.y; sB.z -= b4o.z; sB.w -= b4o.w;
                s02 -= no & 0x00FF00FFu;
                s13 -= (no >> 8) & 0x00FF00FFu;
            }
            if (h - h0 >= 6) {
                float N0 = (float)(s02 & 0xFFFFu);
                float N2 = (float)(s02 >> 16);
                float N1 = (float)(s13 & 0xFFFFu);
                float N3 = (float)(s13 >> 16);
                lsum += s_class(sA.x, sB.x, N0);
                lsum += s_class(sA.y, sB.y, N1);
                lsum += s_class(sA.z, sB.z, N2);
                lsum += s_class(sA.w, sB.w, N3);
            }
        }
    }

    red[tid] = lsum;
    __syncthreads();
    for (int s = 256; s > 0; s >>= 1) {
        if (tid < s && tid + s < 360) red[tid] += red[tid + s];
        __syncthreads();
    }
    if (tid == 0) atomicAdd(&g_acc, (double)red[0]);
}

__global__ void k3(float* __restrict__ out)
{
    // total outputs = 2 * 4 * 154 * 154 * 90 = 17,075,520
    out[0] = (float)(1.0 - g_acc * (1.0 / 17075520.0));
}

extern "C" void kernel_launch(void* const* d_in, const int* in_sizes, int n_in,
                              void* d_out, int out_size)
{
    (void)out_size;
    // Resolve input order by element count (x: 19,660,800 / y: 4,915,200)
    const float* X;
    const int*   Y;
    if (n_in >= 2 && in_sizes[0] == Y_ELEMS) {
        Y = (const int*)d_in[0];
        X = (const float*)d_in[1];
    } else {
        X = (const float*)d_in[0];
        Y = (const int*)d_in[1];
    }

    static int smem_set = 0;
    if (!smem_set) {
        cudaFuncSetAttribute(k1, cudaFuncAttributeMaxDynamicSharedMemorySize, SMEM1);
        smem_set = 1;
    }

    k_probe<<<1, 256>>>(Y);
    k1<<<dim3(8, HH, BB), K1_THREADS, SMEM1>>>(X, Y);
    k2<<<dim3(39, 8, BB), dim3(90, 4, 1)>>>();
    k3<<<1, 1>>>((float*)d_out);
}

// round 8
// speedup vs baseline: 1.0596x; 1.0596x over previous
#include <cuda_runtime.h>
#include <cuda_fp16.h>

// Shapes
#define BB   2
#define CC   4
#define HH   160
#define WW   160
#define DD   96
#define HOUT 154
#define WOUT 154
#define DOUT 90
#define CHST (160*160*96)          // x channel stride (elements)

#define X_ELEMS (BB*CC*HH*WW*DD)   // 19,660,800
#define Y_ELEMS (BB*1*HH*WW*DD)    //  4,915,200

// Intermediate: per (b, h, wo, do): A[4], B[4] (half4 = uint2), N packed (4 x u8)
#define NPOS (BB*HH*WOUT*DOUT)     // 4,435,200

__device__ uint2    g_A[NPOS];
__device__ uint2    g_B[NPOS];
__device__ unsigned g_N[NPOS];
__device__ double   g_acc;
__device__ int      g_ystride;     // 1 = y int32, 2 = y int64 (read low words)

__device__ __forceinline__ __half2 u2h(unsigned u) { return *reinterpret_cast<__half2*>(&u); }
__device__ __forceinline__ unsigned h2u(__half2 h) { return *reinterpret_cast<unsigned*>(&h); }

// ---------------- dtype probe: int64 y has all-zero odd 32-bit words ----------------
__global__ void k_probe(const int* __restrict__ Y)
{
    __shared__ unsigned acc[256];
    unsigned v = 0;
    for (int i = threadIdx.x; i < 4096; i += 256)
        v |= (unsigned)Y[2 * i + 1];
    acc[threadIdx.x] = v;
    __syncthreads();
    for (int s = 128; s > 0; s >>= 1) {
        if (threadIdx.x < s) acc[threadIdx.x] |= acc[threadIdx.x + s];
        __syncthreads();
    }
    if (threadIdx.x == 0) {
        g_ystride = (acc[0] == 0u) ? 2 : 1;
        g_acc = 0.0;
    }
}

// ---------------- K1: expand -> D-window -> W-window (half2 arithmetic) ----------------
#define WOC  20             // output wo per chunk
#define WINC 26             // input w per chunk (WOC+6)
#define K1_THREADS 256

// smem layout (bytes):
//   ea  uint2[WINC*96] = 19968   (per-class A half4)
//   eb  uint2[WINC*96] = 19968   (per-class B half4)
//   en  u32  [WINC*96] =  9984
//   s2a uint2[WINC*90] = 18720
//   s2b uint2[WINC*90] = 18720
//   s2n u32  [WINC*90] =  9360
#define OFF_EB  19968
#define OFF_EN  39936
#define OFF_S2A 49920
#define OFF_S2B 68640
#define OFF_S2N 87360
#define SMEM1   96720

__global__ __launch_bounds__(K1_THREADS) void k1(const float* __restrict__ X,
                                                 const int* __restrict__ Y)
{
    extern __shared__ char sm[];
    uint2*    sea = (uint2*)sm;
    uint2*    seb = (uint2*)(sm + OFF_EB);
    unsigned* sen = (unsigned*)(sm + OFF_EN);
    uint2*    s2a = (uint2*)(sm + OFF_S2A);
    uint2*    s2b = (uint2*)(sm + OFF_S2B);
    unsigned* s2n = (unsigned*)(sm + OFF_S2N);

    const int chunk = blockIdx.x;
    const int h     = blockIdx.y;
    const int b     = blockIdx.z;
    const int wb    = chunk * WOC;
    const int woc   = min(WOC, WOUT - wb);
    const int wic   = woc + 6;
    const int tid   = threadIdx.x;
    const int ys    = g_ystride;

    // ---- Stage A: a = sigmoid(x[y]) - 0.5; expand into class lane of half4 ----
    const float* Xb = X + (size_t)b * 4 * CHST + (size_t)h * (WW * DD);
    const int*   Yb = Y + (size_t)ys * ((size_t)b * ((size_t)HH * WW * DD) + (size_t)h * (WW * DD));
    for (int i = tid; i < wic * 96; i += K1_THREADS) {
        int wl = i / 96;
        int d  = i - wl * 96;
        int off = (wb + wl) * 96 + d;
        int k = Yb[off * ys];
        float x0 = Xb[off];
        float x1 = Xb[off + CHST];
        float x2 = Xb[off + 2 * CHST];
        float x3 = Xb[off + 3 * CHST];
        float v = (k == 0) ? x0 : (k == 1) ? x1 : (k == 2) ? x2 : x3;
        float t = __fdividef(1.0f, 1.0f + __expf(-v));
        float a = t - 0.5f;
        unsigned ha = (unsigned)__half_as_ushort(__float2half_rn(a));
        unsigned hb = (unsigned)__half_as_ushort(__float2half_rn(a * a));
        int sh = (k & 1) ? 16 : 0;
        unsigned sa = ha << sh, sb_ = hb << sh;
        bool hi = (k & 2);
        sea[i] = make_uint2(hi ? 0u : sa, hi ? sa : 0u);
        seb[i] = make_uint2(hi ? 0u : sb_, hi ? sb_ : 0u);
        sen[i] = 1u << (k * 8);
    }
    __syncthreads();

    // ---- Stage B: window-7 sum along D (pure half2 adds) ----
    for (int i = tid; i < wic * 90; i += K1_THREADS) {
        int wl = i / 90;
        int dd = i - wl * 90;
        int base = wl * 96 + dd;
        __half2 A01 = u2h(0), A23 = u2h(0), B01 = u2h(0), B23 = u2h(0);
        unsigned n = 0u;
        #pragma unroll
        for (int j = 0; j < 7; ++j) {
            uint2 ea = sea[base + j];
            uint2 eb = seb[base + j];
            A01 = __hadd2(A01, u2h(ea.x));
            A23 = __hadd2(A23, u2h(ea.y));
            B01 = __hadd2(B01, u2h(eb.x));
            B23 = __hadd2(B23, u2h(eb.y));
            n += sen[base + j];
        }
        s2a[i] = make_uint2(h2u(A01), h2u(A23));
        s2b[i] = make_uint2(h2u(B01), h2u(B23));
        s2n[i] = n;
    }
    __syncthreads();

    // ---- Stage C: window-7 sum along W, write half4 intermediate ----
    for (int i = tid; i < woc * 90; i += K1_THREADS) {
        int wl = i / 90;
        int dd = i - wl * 90;
        __half2 A01 = u2h(0), A23 = u2h(0), B01 = u2h(0), B23 = u2h(0);
        unsigned n = 0u;
        #pragma unroll
        for (int j = 0; j < 7; ++j) {
            int p = (wl + j) * 90 + dd;
            uint2 a2 = s2a[p];
            uint2 b2 = s2b[p];
            A01 = __hadd2(A01, u2h(a2.x));
            A23 = __hadd2(A23, u2h(a2.y));
            B01 = __hadd2(B01, u2h(b2.x));
            B23 = __hadd2(B23, u2h(b2.y));
            n += s2n[p];                   // per-byte max 49, no carry
        }
        size_t g = (((size_t)(b * HH + h)) * WOUT + (wb + wl)) * DOUT + dd;
        g_A[g] = make_uint2(h2u(A01), h2u(A23));
        g_B[g] = make_uint2(h2u(B01), h2u(B23));
        g_N[g] = n;
    }
}

// ---------------- K2: sliding window-7 along H + finalize (single RCP) ----------------
#define SEG 20
#define HS  (WOUT * DOUT)

__device__ __forceinline__ void nd_class(float A, float B, float Nf,
                                         float& num, float& den)
{
    const float inv343 = 1.0f / 343.0f;
    const float K2C = 49.0f / 48.0f;
    const float K4C = K2C * K2C;
    const float Cc  = 0.00045f;            // (0.03*1)^2/2
    float yb  = Nf * inv343;
    float g1  = 1.0f - yb;
    float Ab  = A * inv343;
    float Bb  = B * inv343;
    num = fmaf(K2C * Ab, g1, Cc);
    float var = fmaf(-Ab, Ab, Bb);
    den = fmaf((K4C * var) * yb, g1, Cc);
}

__global__ __launch_bounds__(360) void k2()
{
    __shared__ float red[360];
    const int tx  = threadIdx.x;           // 0..89 -> do
    const int ty  = threadIdx.y;           // 0..3  -> wo offset
    const int tid = ty * 90 + tx;
    const int wo  = blockIdx.x * 4 + ty;
    const int h0  = blockIdx.y * SEG;
    const int b   = blockIdx.z;
    const int segN = min(SEG, HOUT - h0);
    const bool act = (wo < WOUT);

    float4 sA = make_float4(0.f, 0.f, 0.f, 0.f);
    float4 sB = make_float4(0.f, 0.f, 0.f, 0.f);
    unsigned s02 = 0u, s13 = 0u;           // dual 16-bit lanes: classes {0,2},{1,3}
    float lsum = 0.f;

    size_t base = (size_t)b * HH * HS + (size_t)wo * DOUT + tx;

    if (act) {
        for (int h = h0; h < h0 + segN + 6; ++h) {
            size_t g = base + (size_t)h * HS;
            uint2 au = g_A[g];
            uint2 bu = g_B[g];
            unsigned n = g_N[g];
            float2 a01 = __half22float2(u2h(au.x));
            float2 a23 = __half22float2(u2h(au.y));
            float2 b01 = __half22float2(u2h(bu.x));
            float2 b23 = __half22float2(u2h(bu.y));
            sA.x += a01.x; sA.y += a01.y; sA.z += a23.x; sA.w += a23.y;
            sB.x += b01.x; sB.y += b01.y; sB.z += b23.x; sB.w += b23.y;
            s02 += n & 0x00FF00FFu;
            s13 += (n >> 8) & 0x00FF00FFu;

            if (h - h0 >= 7) {
                size_t go = base + (size_t)(h - 7) * HS;
                uint2 auo = g_A[go];
                uint2 buo = g_B[go];
                unsigned no = g_N[go];
                float2 c01 = __half22float2(u2h(auo.x));
                float2 c23 = __half22float2(u2h(auo.y));
                float2 d01 = __half22float2(u2h(buo.x));
                float2 d23 = __half22float2(u2h(buo.y));
                sA.x -= c01.x; sA.y -= c01.y; sA.z -= c23.x; sA.w -= c23.y;
                sB.x -= d01.x; sB.y -= d01.y; sB.z -= d23.x; sB.w -= d23.y;
                s02 -= no & 0x00FF00FFu;
                s13 -= (no >> 8) & 0x00FF00FFu;
            }
            if (h - h0 >= 6) {
                float N0 = (float)(s02 & 0xFFFFu);
                float N2 = (float)(s02 >> 16);
                float N1 = (float)(s13 & 0xFFFFu);
                float N3 = (float)(s13 >> 16);
                float n0, d0, n1, d1, n2, d2, n3, d3;
                nd_class(sA.x, sB.x, N0, n0, d0);
                nd_class(sA.y, sB.y, N1, n1, d1);
                nd_class(sA.z, sB.z, N2, n2, d2);
                nd_class(sA.w, sB.w, N3, n3, d3);
                // single reciprocal over common denominator
                float p01 = d0 * d1, p23 = d2 * d3;
                float num = fmaf(n0, d1, n1 * d0) * p23 + fmaf(n2, d3, n3 * d2) * p01;
                lsum += __fdividef(num, p01 * p23);
            }
        }
    }

    red[tid] = lsum;
    __syncthreads();
    for (int s = 256; s > 0; s >>= 1) {
        if (tid < s && tid + s < 360) red[tid] += red[tid + s];
        __syncthreads();
    }
    if (tid == 0) atomicAdd(&g_acc, (double)red[0]);
}

__global__ void k3(float* __restrict__ out)
{
    out[0] = (float)(1.0 - g_acc * (1.0 / 17075520.0));
}

extern "C" void kernel_launch(void* const* d_in, const int* in_sizes, int n_in,
                              void* d_out, int out_size)
{
    (void)out_size;
    const float* X;
    const int*   Y;
    if (n_in >= 2 && in_sizes[0] == Y_ELEMS) {
        Y = (const int*)d_in[0];
        X = (const float*)d_in[1];
    } else {
        X = (const float*)d_in[0];
        Y = (const int*)d_in[1];
    }

    static int smem_set = 0;
    if (!smem_set) {
        cudaFuncSetAttribute(k1, cudaFuncAttributeMaxDynamicSharedMemorySize, SMEM1);
        smem_set = 1;
    }

    k_probe<<<1, 256>>>(Y);
    k1<<<dim3(8, HH, BB), K1_THREADS, SMEM1>>>(X, Y);
    k2<<<dim3(39, 8, BB), dim3(90, 4, 1)>>>();
    k3<<<1, 1>>>((float*)d_out);
}